// round 5
// baseline (speedup 1.0000x reference)
#include <cuda_runtime.h>
#include <cuda_fp16.h>
#include <cstdint>

#define GN 4096
#define DIN 64
#define DOUT 64
#define TOPK 4
#define SCALE 2048.0f
#define SCALE2 (2048.0f*2048.0f)

// ---------------- scratch (static device globals; no allocs allowed) --------
__device__ __half g_Sh [GN*(size_t)GN];   // S*SCALE, row-major  [i][k]  (32MB)
__device__ __half g_ShT[GN*(size_t)GN];   // S^T*SCALE, row-major [j][k] (32MB)
__device__ float  g_S2 [GN*(size_t)GN];   // (S*SCALE)@(S*SCALE)          (64MB)
__device__ float  g_dinv[GN];
__device__ float  g_rS[GN];     // rowsum(S)           (atomic-accumulated)
__device__ float  g_rs2[GN];    // rowsum(S2)*SCALE2   (atomic-accumulated)
__device__ float  g_dinv2[GN];
__device__ float  g_t[2];
__device__ float  g_y[GN*DOUT];

// ---------------- small helpers --------------------------------------------
__device__ __forceinline__ float blk_reduce_sum(float s) {
    __shared__ float sm[8];
    for (int o = 16; o; o >>= 1) s += __shfl_down_sync(0xffffffffu, s, o);
    if ((threadIdx.x & 31) == 0) sm[threadIdx.x >> 5] = s;
    __syncthreads();
    float v = 0.f;
    if (threadIdx.x < 8) {
        v = sm[threadIdx.x];
        for (int o = 4; o; o >>= 1) v += __shfl_down_sync(0xffu, v, o);
    }
    return v;
}

__global__ void k_zero() {
    int i = blockIdx.x * blockDim.x + threadIdx.x;
    if (i < GN) { g_rS[i] = 0.f; g_rs2[i] = 0.f; }
}

__global__ void k_rowsumA(const float* __restrict__ A) {
    int row = blockIdx.x;
    const float4* Ar = reinterpret_cast<const float4*>(A + (size_t)row * GN);
    float s = 0.f;
    for (int j = threadIdx.x; j < GN / 4; j += blockDim.x) {
        float4 v = Ar[j];
        s += v.x + v.y + v.z + v.w;
    }
    float tot = blk_reduce_sum(s);
    if (threadIdx.x == 0) g_dinv[row] = rsqrtf(tot);
}

// build Sh + ShT (fp16, *SCALE) and accumulate rowsum(S) into g_rS
__global__ void k_build(const float* __restrict__ A) {
    __shared__ float tile[32][33];
    int bx = blockIdx.x, by = blockIdx.y;
    int tx = threadIdx.x, ty = threadIdx.y;
    int col = bx * 32 + tx;
    float dc = g_dinv[col];
#pragma unroll
    for (int r = 0; r < 4; r++) {
        int row = by * 32 + ty + r * 8;
        float v = A[(size_t)row * GN + col] * g_dinv[row] * dc * SCALE;
        tile[ty + r * 8][tx] = v;
        g_Sh[(size_t)row * GN + col] = __float2half_rn(v);
        float ws = v;
        for (int o = 16; o; o >>= 1) ws += __shfl_down_sync(0xffffffffu, ws, o);
        if (tx == 0) atomicAdd(&g_rS[row], ws * (1.0f / SCALE));
    }
    __syncthreads();
#pragma unroll
    for (int r = 0; r < 4; r++) {
        int orow = bx * 32 + ty + r * 8;
        int ocol = by * 32 + tx;
        g_ShT[(size_t)orow * GN + ocol] = __float2half_rn(tile[tx][ty + r * 8]);
    }
}

// ---------------- HMMA GEMM: S2 = Sh @ ShT^T --------------------------------
// CTA tile 256Mx128N, K-chunk 64, 8 warps (warp tile 64x64), 3-stage cp.async,
// SW128-swizzled smem. Epilogue fuses rowsum(S2).
#define ST 3
#define KC 64
#define NC (GN / KC)                 // 64
#define A_BYTES (256 * 128)          // 32KB
#define B_BYTES (128 * 128)          // 16KB
#define STAGE_BYTES (A_BYTES + B_BYTES)
#define DYN_SMEM (ST * STAGE_BYTES)

__device__ __forceinline__ uint32_t sw128(uint32_t off) {
    return off ^ ((off >> 3) & 0x70);
}

__global__ void __launch_bounds__(256, 1) k_gemm() {
    extern __shared__ char dsm[];
    uint32_t sbase;
    asm("{ .reg .u64 t; cvta.to.shared.u64 t, %1; cvt.u32.u64 %0, t; }"
        : "=r"(sbase) : "l"(dsm));

    const __half* Ag = g_Sh;
    const __half* Bg = g_ShT;
    int tid = threadIdx.x, warp = tid >> 5, lane = tid & 31;
    int wm = warp & 3;   // 4 slabs of 64 rows
    int wn = warp >> 2;  // 2 slabs of 64 cols
    int rowBase = blockIdx.y * 256;
    int colBase = blockIdx.x * 128;

    float acc[4][8][4];
#pragma unroll
    for (int a = 0; a < 4; a++)
#pragma unroll
        for (int b = 0; b < 8; b++)
#pragma unroll
            for (int c = 0; c < 4; c++) acc[a][b][c] = 0.f;

    auto load_chunk = [&](int j) {
        uint32_t st0 = sbase + (j % ST) * STAGE_BYTES;
        int k0 = j * KC;
#pragma unroll
        for (int t = 0; t < 12; t++) {
            int q = tid + t * 256;            // 0..3071
            const __half* src;
            uint32_t dst;
            if (q < 2048) {                   // A: 256 rows x 4 x 16B
                int r = q >> 3, c16 = q & 7;
                src = Ag + (size_t)(rowBase + r) * GN + k0 + c16 * 8;
                dst = st0 + sw128(r * 128 + c16 * 16);
            } else {                          // B: 128 rows x 4 x 16B
                int idx = q - 2048;
                int r = idx >> 3, c16 = idx & 7;
                src = Bg + (size_t)(colBase + r) * GN + k0 + c16 * 8;
                dst = st0 + A_BYTES + sw128(r * 128 + c16 * 16);
            }
            asm volatile("cp.async.cg.shared.global [%0],[%1],16;\n" :: "r"(dst), "l"(src));
        }
        asm volatile("cp.async.commit_group;\n");
    };

    load_chunk(0);
    load_chunk(1);

    for (int i = 0; i < NC; i++) {
        if (i + 2 < NC) load_chunk(i + 2);
        else asm volatile("cp.async.commit_group;\n");
        asm volatile("cp.async.wait_group 2;\n");
        __syncthreads();

        uint32_t aB = sbase + (i % ST) * STAGE_BYTES;
        uint32_t bB = aB + A_BYTES;
#pragma unroll
        for (int ks = 0; ks < 4; ks++) {
            int kk = ks * 16;
            uint32_t af[4][4];
#pragma unroll
            for (int mt = 0; mt < 4; mt++) {
                int m = wm * 64 + mt * 16 + (lane & 15);
                uint32_t off = m * 128 + kk * 2 + (lane >> 4) * 16;
                uint32_t addr = aB + sw128(off);
                asm volatile("ldmatrix.sync.aligned.m8n8.x4.shared.b16 {%0,%1,%2,%3},[%4];"
                             : "=r"(af[mt][0]), "=r"(af[mt][1]), "=r"(af[mt][2]), "=r"(af[mt][3])
                             : "r"(addr));
            }
            uint32_t bf[8][2];
#pragma unroll
            for (int nb = 0; nb < 4; nb++) {
                int sel = lane >> 3;
                int nn = wn * 64 + nb * 16 + (sel >> 1) * 8 + (lane & 7);
                uint32_t off = nn * 128 + kk * 2 + (sel & 1) * 16;
                uint32_t addr = bB + sw128(off);
                uint32_t r0, r1, r2, r3;
                asm volatile("ldmatrix.sync.aligned.m8n8.x4.shared.b16 {%0,%1,%2,%3},[%4];"
                             : "=r"(r0), "=r"(r1), "=r"(r2), "=r"(r3) : "r"(addr));
                bf[nb * 2][0] = r0; bf[nb * 2][1] = r1;
                bf[nb * 2 + 1][0] = r2; bf[nb * 2 + 1][1] = r3;
            }
#pragma unroll
            for (int mt = 0; mt < 4; mt++)
#pragma unroll
                for (int nt = 0; nt < 8; nt++) {
                    asm volatile(
                        "mma.sync.aligned.m16n8k16.row.col.f32.f16.f16.f32 "
                        "{%0,%1,%2,%3},{%4,%5,%6,%7},{%8,%9},{%0,%1,%2,%3};"
                        : "+f"(acc[mt][nt][0]), "+f"(acc[mt][nt][1]),
                          "+f"(acc[mt][nt][2]), "+f"(acc[mt][nt][3])
                        : "r"(af[mt][0]), "r"(af[mt][1]), "r"(af[mt][2]), "r"(af[mt][3]),
                          "r"(bf[nt][0]), "r"(bf[nt][1]));
                }
        }
        __syncthreads();
    }

    // epilogue: store + fused rowsum(S2) (quad-reduced, one atomic per row half)
#pragma unroll
    for (int mt = 0; mt < 4; mt++) {
        float rsA = 0.f, rsB = 0.f;
#pragma unroll
        for (int nt = 0; nt < 8; nt++) {
            int m0 = rowBase + wm * 64 + mt * 16 + (lane >> 2);
            int n0 = colBase + wn * 64 + nt * 8 + (lane & 3) * 2;
            *reinterpret_cast<float2*>(g_S2 + (size_t)m0 * GN + n0) =
                make_float2(acc[mt][nt][0], acc[mt][nt][1]);
            *reinterpret_cast<float2*>(g_S2 + (size_t)(m0 + 8) * GN + n0) =
                make_float2(acc[mt][nt][2], acc[mt][nt][3]);
            rsA += acc[mt][nt][0] + acc[mt][nt][1];
            rsB += acc[mt][nt][2] + acc[mt][nt][3];
        }
        rsA += __shfl_xor_sync(0xffffffffu, rsA, 1);
        rsA += __shfl_xor_sync(0xffffffffu, rsA, 2);
        rsB += __shfl_xor_sync(0xffffffffu, rsB, 1);
        rsB += __shfl_xor_sync(0xffffffffu, rsB, 2);
        if ((lane & 3) == 0) {
            int m0 = rowBase + wm * 64 + mt * 16 + (lane >> 2);
            atomicAdd(&g_rs2[m0], rsA);
            atomicAdd(&g_rs2[m0 + 8], rsB);
        }
    }
}

__global__ void k_sig(const float* __restrict__ theta) {
    if (threadIdx.x < 2) g_t[threadIdx.x] = 1.0f / (1.0f + expf(-theta[threadIdx.x]));
}

__global__ void k_d2() {
    int i = blockIdx.x * blockDim.x + threadIdx.x;
    if (i < GN) {
        float d2 = 1.0f + g_t[0] * g_rS[i] + g_t[1] * (g_rs2[i] * (1.0f / SCALE2));
        g_dinv2[i] = rsqrtf(d2);
    }
}

// y = x @ W^T
__global__ void k_xw(const float* __restrict__ x, const float* __restrict__ W) {
    __shared__ float Wt[DIN * DOUT];
    __shared__ float xr[DIN];
    int row = blockIdx.x;
    for (int i = threadIdx.x; i < DOUT * DIN; i += 64) {
        int c = i / DIN, d = i % DIN;
        Wt[d * DOUT + c] = W[i];
    }
    if (threadIdx.x < DIN) xr[threadIdx.x] = x[row * DIN + threadIdx.x];
    __syncthreads();
    int c = threadIdx.x;
    float s = 0.f;
#pragma unroll
    for (int d = 0; d < DIN; d++) s += xr[d] * Wt[d * DOUT + c];
    g_y[row * DOUT + c] = s;
}

// ---------------- top-4 per row + sparse output -----------------------------
__device__ __forceinline__ void topk_insert(float c, int j, float* v, int* id) {
    if (c > v[3] || (c == v[3] && j < id[3])) {
        v[3] = c; id[3] = j;
#pragma unroll
        for (int s = 3; s > 0; s--) {
            if (v[s] > v[s - 1] || (v[s] == v[s - 1] && id[s] < id[s - 1])) {
                float tv = v[s]; v[s] = v[s - 1]; v[s - 1] = tv;
                int ti = id[s]; id[s] = id[s - 1]; id[s - 1] = ti;
            }
        }
    }
}

__global__ void k_topk(const float* __restrict__ A, const float* __restrict__ b,
                       float* __restrict__ out) {
    int i   = blockIdx.x;
    int tid = threadIdx.x;
    float t0  = g_t[0];
    float t1s = g_t[1] * (1.0f / SCALE2);
    float di  = g_dinv[i];
    const float* Ar = A    + (size_t)i * GN;
    const float* Sr = g_S2 + (size_t)i * GN;

    float vb[4] = {-1e30f, -1e30f, -1e30f, -1e30f};
    int   ib[4] = {0x7fffffff, 0x7fffffff, 0x7fffffff, 0x7fffffff};

    for (int j = tid; j < GN; j += 128) {
        float p = t0 * (Ar[j] * di * g_dinv[j]) + t1s * Sr[j];
        if (j == i) p += 1.0f;
        float c = p * g_dinv2[j];
        topk_insert(c, j, vb, ib);
    }

    __shared__ float sv[128 * 4];
    __shared__ int   si[128 * 4];
#pragma unroll
    for (int s = 0; s < 4; s++) { sv[tid * 4 + s] = vb[s]; si[tid * 4 + s] = ib[s]; }
    __syncthreads();

    __shared__ float fv[4];
    __shared__ int   fi[4];
    if (tid == 0) {
        float bv[4] = {-1e30f, -1e30f, -1e30f, -1e30f};
        int   bi[4] = {0x7fffffff, 0x7fffffff, 0x7fffffff, 0x7fffffff};
        for (int q = 0; q < 128 * 4; q++) topk_insert(sv[q], si[q], bv, bi);
#pragma unroll
        for (int s = 0; s < 4; s++) { fv[s] = bv[s]; fi[s] = bi[s]; }
    }
    __syncthreads();

    if (tid < DOUT) {
        float di2 = g_dinv2[i];
        float s = b[tid];
#pragma unroll
        for (int q = 0; q < TOPK; q++)
            s += di2 * fv[q] * g_y[fi[q] * DOUT + tid];
        out[(size_t)i * DOUT + tid] = s;
    }
}

// ---------------- launch -----------------------------------------------------
extern "C" void kernel_launch(void* const* d_in, const int* in_sizes, int n_in,
                              void* d_out, int out_size) {
    const float* x     = (const float*)d_in[0];
    const float* A     = (const float*)d_in[1];
    const float* theta = (const float*)d_in[2];
    const float* W     = (const float*)d_in[3];
    const float* b     = (const float*)d_in[4];
    float* out = (float*)d_out;

    cudaFuncSetAttribute(k_gemm, cudaFuncAttributeMaxDynamicSharedMemorySize, DYN_SMEM);

    k_zero<<<(GN + 255) / 256, 256>>>();
    k_rowsumA<<<GN, 256>>>(A);
    k_sig<<<1, 32>>>(theta);
    k_build<<<dim3(128, 128), dim3(32, 8)>>>(A);
    k_gemm<<<dim3(GN / 128, GN / 256), 256, DYN_SMEM>>>();
    k_d2<<<16, 256>>>();
    k_xw<<<GN, 64>>>(x, W);
    k_topk<<<GN, 128>>>(A, b, out);
}